// round 3
// baseline (speedup 1.0000x reference)
#include <cuda_runtime.h>
#include <math.h>

// Problem constants
#define MM    35637
#define KKN   20
#define MKP   712740          // MM*KKN points
#define NNF   15872
#define FEATC 128
#define EPSB  1e-5
#define PAD   132             // smem row pitch (floats): 16B-aligned rows, low bank conflicts
#define NBLK  5569            // ceil(MKP/128)

typedef unsigned long long ull;

// ---------------- device scratch (static: allocation-guard-safe) ----------------
__device__ float  g_h[91230720];     // 712740 x 128 pre-activations (in-place ping)
__device__ double g_sum[8 * 128];
__device__ double g_ssq[8 * 128];
__device__ float  g_scale[8 * 128];
__device__ float  g_shift[8 * 128];
__device__ double g_inS[7];
__device__ double g_inSS[28];

// ---------------- f32x2 helpers ----------------
__device__ __forceinline__ ull pack2(float x) {
    ull r;
    asm("mov.b64 %0, {%1, %1};" : "=l"(r) : "r"(__float_as_uint(x)));
    return r;
}
__device__ __forceinline__ ull fma2(ull a, ull b, ull c) {
    ull d;
    asm("fma.rn.f32x2 %0, %1, %2, %3;" : "=l"(d) : "l"(a), "l"(b), "l"(c));
    return d;
}
__device__ __forceinline__ float2 unpk(ull v) {
    unsigned lo, hi;
    asm("mov.b64 {%0, %1}, %2;" : "=r"(lo), "=r"(hi) : "l"(v));
    float2 r;
    r.x = __uint_as_float(lo);
    r.y = __uint_as_float(hi);
    return r;
}

// ---------------- zero accumulators (must rerun every graph replay) ----------------
__global__ void k_zero() {
    int t = threadIdx.x;
    for (int i = t; i < 1024; i += 256) { g_sum[i] = 0.0; g_ssq[i] = 0.0; }
    if (t < 7)  g_inS[t]  = 0.0;
    if (t < 28) g_inSS[t] = 0.0;
}

// ---------------- input stats: sum(x) [7] and sum(x x^T) [28 triangle] ----------------
__global__ void k_instats(const float* __restrict__ in7) {
    long stride = (long)gridDim.x * blockDim.x;
    float s[7], q[28];
#pragma unroll
    for (int j = 0; j < 7; j++) s[j] = 0.f;
#pragma unroll
    for (int t = 0; t < 28; t++) q[t] = 0.f;

    for (long p = (long)blockIdx.x * blockDim.x + threadIdx.x; p < MKP; p += stride) {
        float x[7];
#pragma unroll
        for (int j = 0; j < 7; j++) x[j] = in7[(long)j * MKP + p];
        int t = 0;
#pragma unroll
        for (int j = 0; j < 7; j++) {
            s[j] += x[j];
#pragma unroll
            for (int jj = j; jj < 7; jj++) { q[t] += x[j] * x[jj]; t++; }
        }
    }
#pragma unroll
    for (int j = 0; j < 7; j++)
        for (int off = 16; off; off >>= 1) s[j] += __shfl_down_sync(0xffffffffu, s[j], off);
#pragma unroll
    for (int t = 0; t < 28; t++)
        for (int off = 16; off; off >>= 1) q[t] += __shfl_down_sync(0xffffffffu, q[t], off);

    if ((threadIdx.x & 31) == 0) {
#pragma unroll
        for (int j = 0; j < 7; j++) atomicAdd(&g_inS[j], (double)s[j]);
#pragma unroll
        for (int t = 0; t < 28; t++) atomicAdd(&g_inSS[t], (double)q[t]);
    }
}

// ---------------- BN0 params analytically from input moments ----------------
__global__ void k_fin0(const float* __restrict__ W0,
                       const float* __restrict__ gammas,
                       const float* __restrict__ betas) {
    int c = threadIdx.x;  // 128
    double S[7], SS[7][7];
#pragma unroll
    for (int j = 0; j < 7; j++) S[j] = g_inS[j];
    int t = 0;
    for (int j = 0; j < 7; j++)
        for (int jj = j; jj < 7; jj++) { SS[j][jj] = g_inSS[t]; SS[jj][j] = g_inSS[t]; t++; }
    double w[7];
#pragma unroll
    for (int j = 0; j < 7; j++) w[j] = (double)W0[c * 7 + j];
    double mu = 0.0;
#pragma unroll
    for (int j = 0; j < 7; j++) mu += w[j] * S[j];
    mu /= (double)MKP;
    double e2 = 0.0;
    for (int j = 0; j < 7; j++)
        for (int jj = 0; jj < 7; jj++) e2 += w[j] * w[jj] * SS[j][jj];
    e2 /= (double)MKP;
    double var = e2 - mu * mu;
    double scl = (double)gammas[c] / sqrt(var + EPSB);
    g_scale[c] = (float)scl;
    g_shift[c] = (float)((double)betas[c] - mu * scl);
}

// ---------------- BN params for layer L from accumulated sums ----------------
__global__ void k_fin(int L, const float* __restrict__ gammas, const float* __restrict__ betas) {
    int c = threadIdx.x;  // 128
    double mu  = g_sum[L * 128 + c] / (double)MKP;
    double var = g_ssq[L * 128 + c] / (double)MKP - mu * mu;
    double scl = (double)gammas[L * 128 + c] / sqrt(var + EPSB);
    g_scale[L * 128 + c] = (float)scl;
    g_shift[L * 128 + c] = (float)((double)betas[L * 128 + c] - mu * scl);
}

// ---------------- fused pass: act_{l-1} = sin(BN(h_{l-1})); h_l = W @ act; stats(h_l) ----------------
// mode 0: build act from raw 7-channel input via conv0 (layer-0 activation)
// mode 1: build act from g_h rows (in-place)
// smem layout (floats): As[128*PAD] | Ws[128*PAD] | red[256] | scs[128] | shs[128] | xs[128*8] | w0s[128*8]
#define SMEM_FLOATS (128 * PAD * 2 + 256 + 256 + 1024 + 1024)

__global__ void __launch_bounds__(256, 1)
k_gemm(const float* __restrict__ src, const float* __restrict__ W,
       const float* __restrict__ W0c, int actL, int statL, int mode) {
    extern __shared__ float sm[];
    float* As  = sm;
    float* Ws  = sm + 128 * PAD;
    float* red = Ws + 128 * PAD;
    float* scs = red + 256;
    float* shs = scs + 128;
    float* xs  = shs + 128;
    float* w0s = xs + 1024;

    const int tid = threadIdx.x;
    const long p0 = (long)blockIdx.x * 128;

    if (tid < 128) {
        scs[tid] = g_scale[actL * 128 + tid];
        shs[tid] = g_shift[actL * 128 + tid];
        red[tid] = 0.f;
        red[128 + tid] = 0.f;
    }
    // W^T tile: Ws[c*PAD + o] = W[o*128 + c]
    for (int i = tid; i < 16384; i += 256) {
        int c = i & 127, o = i >> 7;
        Ws[c * PAD + o] = W[o * 128 + c];
    }
    if (mode == 0) {
        for (int t = tid; t < 896; t += 256) w0s[(t / 7) * 8 + (t % 7)] = W0c[t];
        for (int t = tid; t < 7 * 128; t += 256) {
            int j = t >> 7, p = t & 127;
            long pg = p0 + p;
            xs[p * 8 + j] = (pg < MKP) ? src[(long)j * MKP + pg] : 0.f;
        }
    }
    __syncthreads();

    // Build activation tile (k-major): As[c*PAD + p] = sin(scale*h_prev + shift)
    if (mode == 0) {
        for (int i = tid; i < 16384; i += 256) {
            int c = i & 127, p = i >> 7;
            const float* xp = xs + p * 8;
            const float* wc = w0s + c * 8;
            float v = 0.f;
#pragma unroll
            for (int j = 0; j < 7; j++) v = fmaf(wc[j], xp[j], v);
            float a = sinf(fmaf(scs[c], v, shs[c]));
            As[c * PAD + p] = (p0 + p < MKP) ? a : 0.f;
        }
    } else {
        for (int i = tid; i < 16384; i += 256) {
            int c = i & 127, p = i >> 7;
            long pg = p0 + p;
            float v = (pg < MKP) ? g_h[pg * 128 + c] : 0.f;
            float a = sinf(fmaf(scs[c], v, shs[c]));
            As[c * PAD + p] = (pg < MKP) ? a : 0.f;
        }
    }
    __syncthreads();

    // 128x128 GEMM: C[p][o] = sum_c act[p][c] * W[o][c], f32x2-packed over point pairs
    const int tx = tid & 15, ty = tid >> 4;
    ull acc[8][4];
#pragma unroll
    for (int j = 0; j < 8; j++)
#pragma unroll
        for (int i = 0; i < 4; i++) acc[j][i] = 0ull;

#pragma unroll 4
    for (int kk = 0; kk < 128; kk++) {
        const float* ar = As + kk * PAD + ty * 8;
        const float* br = Ws + kk * PAD + tx * 8;
        ull a0 = ((const ull*)ar)[0];
        ull a1 = ((const ull*)ar)[1];
        ull a2 = ((const ull*)ar)[2];
        ull a3 = ((const ull*)ar)[3];
        float4 bv0 = *(const float4*)(br);
        float4 bv1 = *(const float4*)(br + 4);
        float b[8] = {bv0.x, bv0.y, bv0.z, bv0.w, bv1.x, bv1.y, bv1.z, bv1.w};
#pragma unroll
        for (int j = 0; j < 8; j++) {
            ull bb = pack2(b[j]);
            acc[j][0] = fma2(a0, bb, acc[j][0]);
            acc[j][1] = fma2(a1, bb, acc[j][1]);
            acc[j][2] = fma2(a2, bb, acc[j][2]);
            acc[j][3] = fma2(a3, bb, acc[j][3]);
        }
    }

    // Epilogue: write h_l in place + per-channel stats
    float s[8], q[8];
#pragma unroll
    for (int j = 0; j < 8; j++) { s[j] = 0.f; q[j] = 0.f; }

#pragma unroll
    for (int i2 = 0; i2 < 4; i2++) {
        float2 v[8];
#pragma unroll
        for (int j = 0; j < 8; j++) v[j] = unpk(acc[j][i2]);
        long pg0 = p0 + ty * 8 + i2 * 2;
        if (pg0 < MKP) {
            float* dst = g_h + pg0 * 128 + tx * 8;
            *(float4*)dst       = make_float4(v[0].x, v[1].x, v[2].x, v[3].x);
            *(float4*)(dst + 4) = make_float4(v[4].x, v[5].x, v[6].x, v[7].x);
#pragma unroll
            for (int j = 0; j < 8; j++) { s[j] += v[j].x; q[j] += v[j].x * v[j].x; }
        }
        if (pg0 + 1 < MKP) {
            float* dst = g_h + (pg0 + 1) * 128 + tx * 8;
            *(float4*)dst       = make_float4(v[0].y, v[1].y, v[2].y, v[3].y);
            *(float4*)(dst + 4) = make_float4(v[4].y, v[5].y, v[6].y, v[7].y);
#pragma unroll
            for (int j = 0; j < 8; j++) { s[j] += v[j].y; q[j] += v[j].y * v[j].y; }
        }
    }
#pragma unroll
    for (int j = 0; j < 8; j++) {
        atomicAdd(&red[tx * 8 + j], s[j]);
        atomicAdd(&red[128 + tx * 8 + j], q[j]);
    }
    __syncthreads();
    if (tid < 128) {
        atomicAdd(&g_sum[statL * 128 + tid], (double)red[tid]);
        atomicAdd(&g_ssq[statL * 128 + tid], (double)red[128 + tid]);
    }
}

// ---------------- final: act7 -> logits -> softmax(K) -> gather+weighted sum ----------------
__global__ void k_final(const float* __restrict__ xfeat, const int* __restrict__ idx,
                        const float* __restrict__ fw, const float* __restrict__ fb,
                        float* __restrict__ out) {
    __shared__ float prod[20][128];
    __shared__ float wsm[20];
    __shared__ float logit[20];
    __shared__ int   idxs[20];

    const int m = blockIdx.x;
    const int tid = threadIdx.x;  // 128
    const float sc = g_scale[7 * 128 + tid];
    const float sh = g_shift[7 * 128 + tid];
    const float f  = fw[tid];
    const float* hrow = g_h + (long)m * 20 * 128;

    if (tid < 20) idxs[tid] = idx[m * 20 + tid];
#pragma unroll
    for (int k = 0; k < 20; k++) {
        float v = hrow[k * 128 + tid];
        prod[k][tid] = sinf(fmaf(sc, v, sh)) * f;
    }
    __syncthreads();

    const int w = tid >> 5, lane = tid & 31;
    for (int k = w; k < 20; k += 4) {
        float sum = prod[k][lane] + prod[k][lane + 32] + prod[k][lane + 64] + prod[k][lane + 96];
        for (int off = 16; off; off >>= 1) sum += __shfl_down_sync(0xffffffffu, sum, off);
        if (lane == 0) logit[k] = sum + fb[0];
    }
    __syncthreads();

    if (tid < 32) {
        float l = (tid < 20) ? logit[tid] : -INFINITY;
        float mx = l;
        for (int off = 16; off; off >>= 1) mx = fmaxf(mx, __shfl_xor_sync(0xffffffffu, mx, off));
        float e = (tid < 20) ? expf(l - mx) : 0.f;
        float ss = e;
        for (int off = 16; off; off >>= 1) ss += __shfl_xor_sync(0xffffffffu, ss, off);
        if (tid < 20) wsm[tid] = e / ss;
    }
    __syncthreads();

    float acc = 0.f;
#pragma unroll
    for (int k = 0; k < 20; k++)
        acc += wsm[k] * xfeat[(long)idxs[k] * 128 + tid];
    out[(long)m * 128 + tid] = acc;
}

// ---------------- launch ----------------
extern "C" void kernel_launch(void* const* d_in, const int* in_sizes, int n_in,
                              void* d_out, int out_size) {
    const float* xfeat  = (const float*)d_in[0];  // (1, N, 128)
    const float* w_up   = (const float*)d_in[1];  // (1, 7, M, K)
    const int*   idx    = (const int*)d_in[2];    // (1, M, K)
    const float* conv0  = (const float*)d_in[3];  // (128, 7)
    const float* convs  = (const float*)d_in[4];  // (7, 128, 128)
    const float* gammas = (const float*)d_in[5];  // (8, 128)
    const float* betas  = (const float*)d_in[6];  // (8, 128)
    const float* fw     = (const float*)d_in[7];  // (1, 128)
    const float* fb     = (const float*)d_in[8];  // (1,)
    float* out = (float*)d_out;

    const int smem_bytes = SMEM_FLOATS * sizeof(float);
    cudaFuncSetAttribute(k_gemm, cudaFuncAttributeMaxDynamicSharedMemorySize, smem_bytes);

    k_zero<<<1, 256>>>();
    k_instats<<<256, 256>>>(w_up);
    k_fin0<<<1, 128>>>(conv0, gammas, betas);

    // Layer 1: act0 from raw input (conv0 + BN0 + sin), GEMM with convs_w[0], stats -> layer 1
    k_gemm<<<NBLK, 256, smem_bytes>>>(w_up, convs, conv0, 0, 1, 0);
    k_fin<<<1, 128>>>(1, gammas, betas);

    // Layers 2..7
    for (int i = 2; i <= 7; i++) {
        k_gemm<<<NBLK, 256, smem_bytes>>>(nullptr, convs + (i - 1) * 16384, nullptr, i - 1, i, 1);
        k_fin<<<1, 128>>>(i, gammas, betas);
    }

    k_final<<<MM, 128>>>(xfeat, idx, fw, fb, out);
}

// round 5
// speedup vs baseline: 1.2944x; 1.2944x over previous
#include <cuda_runtime.h>
#include <math.h>
#include <stdint.h>

// Problem constants
#define MM    35637
#define KKN   20
#define MKP   712740          // MM*KKN points
#define EPSB  1e-5
#define NBLK  5569            // ceil(MKP/128)
#define PK    132             // smem pitch (floats) for As/Bs: 132*4=528B, 16B-aligned rows

typedef unsigned int u32;

// ---------------- device scratch (static: allocation-guard-safe) ----------------
__device__ float  g_h[91230720];     // 712740 x 128 pre-activations (in-place)
__device__ double g_sum[8 * 128];
__device__ double g_ssq[8 * 128];
__device__ float  g_scale[8 * 128];
__device__ float  g_shift[8 * 128];
__device__ double g_inS[7];
__device__ double g_inSS[28];

// ---------------- smem layout (floats) ----------------
// As[128][PK] | Bs[128][PK] | red[256] | scs[128] | shs[128] | xs0[128*12] | w0s[128*12]
#define OFF_AS   0
#define OFF_BS   (128 * PK)
#define OFF_RED  (2 * 128 * PK)
#define OFF_SC   (OFF_RED + 256)
#define OFF_SH   (OFF_SC + 128)
#define OFF_XS   (OFF_SH + 128)
#define OFF_W0   (OFF_XS + 128 * 12)
#define SMEM_FLOATS (OFF_W0 + 128 * 12)

// ---------------- helpers ----------------
static __device__ __forceinline__ u32 tf32r(float x) {
    u32 r;
    asm("cvt.rna.tf32.f32 %0, %1;" : "=r"(r) : "f"(x));
    return r;
}
static __device__ __forceinline__ void split2(float x, u32& hi, u32& lo) {
    u32 h = tf32r(x);
    hi = h;
    lo = tf32r(x - __uint_as_float(h));
}
static __device__ __forceinline__ void mma8(float* c, const u32* a, const u32* b) {
    asm volatile(
        "mma.sync.aligned.m16n8k8.row.col.f32.tf32.tf32.f32 "
        "{%0,%1,%2,%3}, {%4,%5,%6,%7}, {%8,%9}, {%0,%1,%2,%3};"
        : "+f"(c[0]), "+f"(c[1]), "+f"(c[2]), "+f"(c[3])
        : "r"(a[0]), "r"(a[1]), "r"(a[2]), "r"(a[3]), "r"(b[0]), "r"(b[1]));
}

// ---------------- zero accumulators (must rerun every graph replay) ----------------
__global__ void k_zero() {
    int t = threadIdx.x;
    for (int i = t; i < 1024; i += 256) { g_sum[i] = 0.0; g_ssq[i] = 0.0; }
    if (t < 7)  g_inS[t]  = 0.0;
    if (t < 28) g_inSS[t] = 0.0;
}

// ---------------- input stats: sum(x) [7] and sum(x x^T) [28 triangle] ----------------
__global__ void k_instats(const float* __restrict__ in7) {
    long stride = (long)gridDim.x * blockDim.x;
    float s[7], q[28];
#pragma unroll
    for (int j = 0; j < 7; j++) s[j] = 0.f;
#pragma unroll
    for (int t = 0; t < 28; t++) q[t] = 0.f;

    for (long p = (long)blockIdx.x * blockDim.x + threadIdx.x; p < MKP; p += stride) {
        float x[7];
#pragma unroll
        for (int j = 0; j < 7; j++) x[j] = in7[(long)j * MKP + p];
        int t = 0;
#pragma unroll
        for (int j = 0; j < 7; j++) {
            s[j] += x[j];
#pragma unroll
            for (int jj = j; jj < 7; jj++) { q[t] += x[j] * x[jj]; t++; }
        }
    }
#pragma unroll
    for (int j = 0; j < 7; j++)
        for (int off = 16; off; off >>= 1) s[j] += __shfl_down_sync(0xffffffffu, s[j], off);
#pragma unroll
    for (int t = 0; t < 28; t++)
        for (int off = 16; off; off >>= 1) q[t] += __shfl_down_sync(0xffffffffu, q[t], off);

    if ((threadIdx.x & 31) == 0) {
#pragma unroll
        for (int j = 0; j < 7; j++) atomicAdd(&g_inS[j], (double)s[j]);
#pragma unroll
        for (int t = 0; t < 28; t++) atomicAdd(&g_inSS[t], (double)q[t]);
    }
}

// ---------------- BN0 params analytically from input moments ----------------
__global__ void k_fin0(const float* __restrict__ W0,
                       const float* __restrict__ gammas,
                       const float* __restrict__ betas) {
    int c = threadIdx.x;  // 128
    double S[7], SS[7][7];
#pragma unroll
    for (int j = 0; j < 7; j++) S[j] = g_inS[j];
    int t = 0;
    for (int j = 0; j < 7; j++)
        for (int jj = j; jj < 7; jj++) { SS[j][jj] = g_inSS[t]; SS[jj][j] = g_inSS[t]; t++; }
    double w[7];
#pragma unroll
    for (int j = 0; j < 7; j++) w[j] = (double)W0[c * 7 + j];
    double mu = 0.0;
#pragma unroll
    for (int j = 0; j < 7; j++) mu += w[j] * S[j];
    mu /= (double)MKP;
    double e2 = 0.0;
    for (int j = 0; j < 7; j++)
        for (int jj = 0; jj < 7; jj++) e2 += w[j] * w[jj] * SS[j][jj];
    e2 /= (double)MKP;
    double var = e2 - mu * mu;
    double scl = (double)gammas[c] / sqrt(var + EPSB);
    g_scale[c] = (float)scl;
    g_shift[c] = (float)((double)betas[c] - mu * scl);
}

// ---------------- BN params for layer L ----------------
__global__ void k_fin(int L, const float* __restrict__ gammas, const float* __restrict__ betas) {
    int c = threadIdx.x;  // 128
    double mu  = g_sum[L * 128 + c] / (double)MKP;
    double var = g_ssq[L * 128 + c] / (double)MKP - mu * mu;
    double scl = (double)gammas[L * 128 + c] / sqrt(var + EPSB);
    g_scale[L * 128 + c] = (float)scl;
    g_shift[L * 128 + c] = (float)((double)betas[L * 128 + c] - mu * scl);
}

// ---------------- fused pass via mma.sync tf32 (2-term split => ~fp32 accuracy) ----------------
// act_{l-1} = __sinf(BN(h_{l-1})) staged fp32 in smem; h_l = act @ W^T via
// m16n8k8 tf32 mma (3 split passes); epilogue writes h_l to g_h + per-channel stats.
__global__ void __launch_bounds__(256, 1)
k_gemm(const float* __restrict__ src, const float* __restrict__ W,
       const float* __restrict__ W0c, int actL, int statL, int mode) {
    extern __shared__ float sm[];
    float* As  = sm + OFF_AS;
    float* Bs  = sm + OFF_BS;
    float* red = sm + OFF_RED;
    float* scs = sm + OFF_SC;
    float* shs = sm + OFF_SH;
    float* xs0 = sm + OFF_XS;
    float* w0s = sm + OFF_W0;

    const int tid  = threadIdx.x;
    const int wid  = tid >> 5;
    const int lane = tid & 31;
    const int wm   = wid & 3;      // M quadrant (32 rows)
    const int wn   = wid >> 2;     // N half (64 cols)
    const int lg   = lane >> 2;    // group id 0..7
    const int lq   = lane & 3;     // quad id 0..3
    const long p0  = (long)blockIdx.x * 128;

    red[tid] = 0.f;
    if (tid < 128) {
        scs[tid] = g_scale[actL * 128 + tid];
        shs[tid] = g_shift[actL * 128 + tid];
    }
    // B tile: W[o][k] fp32, pitch PK (vectorized)
    for (int it = tid; it < 4096; it += 256) {
        int o = it >> 5, k = (it & 31) << 2;
        *(float4*)&Bs[o * PK + k] = *(const float4*)&W[o * 128 + k];
    }
    if (mode == 0) {
        for (int t = tid; t < 1024; t += 256) {
            int p = t >> 3, j = t & 7;
            xs0[p * 12 + j] = (j < 7 && p0 + p < MKP) ? src[(long)j * MKP + p0 + p] : 0.f;
        }
        for (int t = tid; t < 1024; t += 256) {
            int c = t >> 3, j = t & 7;
            w0s[c * 12 + j] = (j < 7) ? W0c[c * 7 + j] : 0.f;
        }
    }
    __syncthreads();

    // ---- build activation tile As[p][c] (fp32) ----
    if (mode == 0) {
        // h0 = conv0 . x via one k=8 split-tf32 mma sweep, then act in regs -> As
        float h0[2][8][4];
#pragma unroll
        for (int mt = 0; mt < 2; mt++)
#pragma unroll
            for (int nt = 0; nt < 8; nt++)
#pragma unroll
                for (int e = 0; e < 4; e++) h0[mt][nt][e] = 0.f;

        u32 ah[2][4], al[2][4];
#pragma unroll
        for (int mt = 0; mt < 2; mt++) {
            int r = wm * 32 + mt * 16 + lg;
            split2(xs0[r * 12 + lq],           ah[mt][0], al[mt][0]);
            split2(xs0[(r + 8) * 12 + lq],     ah[mt][1], al[mt][1]);
            split2(xs0[r * 12 + lq + 4],       ah[mt][2], al[mt][2]);
            split2(xs0[(r + 8) * 12 + lq + 4], ah[mt][3], al[mt][3]);
        }
#pragma unroll
        for (int nt = 0; nt < 8; nt++) {
            int n = wn * 64 + nt * 8 + lg;
            u32 bh[2], bl[2];
            split2(w0s[n * 12 + lq],     bh[0], bl[0]);
            split2(w0s[n * 12 + lq + 4], bh[1], bl[1]);
#pragma unroll
            for (int mt = 0; mt < 2; mt++) {
                mma8(h0[mt][nt], ah[mt], bh);
                mma8(h0[mt][nt], ah[mt], bl);
                mma8(h0[mt][nt], al[mt], bh);
            }
        }
#pragma unroll
        for (int mt = 0; mt < 2; mt++) {
            int rA = wm * 32 + mt * 16 + lg;
            int rB = rA + 8;
            bool vA = (p0 + rA < MKP), vB = (p0 + rB < MKP);
#pragma unroll
            for (int nt = 0; nt < 8; nt++) {
                int c0 = wn * 64 + nt * 8 + lq * 2;
                As[rA * PK + c0]     = vA ? __sinf(fmaf(scs[c0],     h0[mt][nt][0], shs[c0]))     : 0.f;
                As[rA * PK + c0 + 1] = vA ? __sinf(fmaf(scs[c0 + 1], h0[mt][nt][1], shs[c0 + 1])) : 0.f;
                As[rB * PK + c0]     = vB ? __sinf(fmaf(scs[c0],     h0[mt][nt][2], shs[c0]))     : 0.f;
                As[rB * PK + c0 + 1] = vB ? __sinf(fmaf(scs[c0 + 1], h0[mt][nt][3], shs[c0 + 1])) : 0.f;
            }
        }
    } else {
        for (int it = tid; it < 4096; it += 256) {
            int p = it >> 5, c = (it & 31) << 2;
            long pg = p0 + p;
            float4 a;
            if (pg < MKP) {
                float4 hv = *(const float4*)&g_h[pg * 128 + c];
                a.x = __sinf(fmaf(scs[c],     hv.x, shs[c]));
                a.y = __sinf(fmaf(scs[c + 1], hv.y, shs[c + 1]));
                a.z = __sinf(fmaf(scs[c + 2], hv.z, shs[c + 2]));
                a.w = __sinf(fmaf(scs[c + 3], hv.w, shs[c + 3]));
            } else {
                a = make_float4(0.f, 0.f, 0.f, 0.f);
            }
            *(float4*)&As[p * PK + c] = a;
        }
    }
    __syncthreads();

    // ---- main GEMM: 128x128x128, split-tf32 mma ----
    float acc[2][8][4];
#pragma unroll
    for (int mt = 0; mt < 2; mt++)
#pragma unroll
        for (int nt = 0; nt < 8; nt++)
#pragma unroll
            for (int e = 0; e < 4; e++) acc[mt][nt][e] = 0.f;

#pragma unroll 1
    for (int ks = 0; ks < 16; ks++) {
        int k0 = ks * 8 + lq;
        u32 ah[2][4], al[2][4];
#pragma unroll
        for (int mt = 0; mt < 2; mt++) {
            int r = wm * 32 + mt * 16 + lg;
            split2(As[r * PK + k0],           ah[mt][0], al[mt][0]);
            split2(As[(r + 8) * PK + k0],     ah[mt][1], al[mt][1]);
            split2(As[r * PK + k0 + 4],       ah[mt][2], al[mt][2]);
            split2(As[(r + 8) * PK + k0 + 4], ah[mt][3], al[mt][3]);
        }
#pragma unroll
        for (int nt = 0; nt < 8; nt++) {
            int n = wn * 64 + nt * 8 + lg;
            u32 bh[2], bl[2];
            split2(Bs[n * PK + k0],     bh[0], bl[0]);
            split2(Bs[n * PK + k0 + 4], bh[1], bl[1]);
#pragma unroll
            for (int mt = 0; mt < 2; mt++) {
                mma8(acc[mt][nt], ah[mt], bh);
                mma8(acc[mt][nt], ah[mt], bl);
                mma8(acc[mt][nt], al[mt], bh);
            }
        }
    }

    // ---- epilogue: write h_l + per-channel stats ----
#pragma unroll
    for (int mt = 0; mt < 2; mt++) {
        long rA = p0 + wm * 32 + mt * 16 + lg;
        long rB = rA + 8;
        bool vA = (rA < MKP), vB = (rB < MKP);
#pragma unroll
        for (int nt = 0; nt < 8; nt++) {
            int c0 = wn * 64 + nt * 8 + lq * 2;
            if (vA) *(float2*)&g_h[rA * 128 + c0] = make_float2(acc[mt][nt][0], acc[mt][nt][1]);
            if (vB) *(float2*)&g_h[rB * 128 + c0] = make_float2(acc[mt][nt][2], acc[mt][nt][3]);
        }
    }
#pragma unroll
    for (int nt = 0; nt < 8; nt++) {
        int c0 = wn * 64 + nt * 8 + lq * 2;
#pragma unroll
        for (int par = 0; par < 2; par++) {
            float v0 = acc[0][nt][par], v1 = acc[0][nt][2 + par];
            float v2 = acc[1][nt][par], v3 = acc[1][nt][2 + par];
            float s = v0 + v1 + v2 + v3;
            float q = fmaf(v0, v0, fmaf(v1, v1, fmaf(v2, v2, v3 * v3)));
            atomicAdd(&red[c0 + par], s);
            atomicAdd(&red[128 + c0 + par], q);
        }
    }
    __syncthreads();
    if (tid < 128) {
        atomicAdd(&g_sum[statL * 128 + tid], (double)red[tid]);
        atomicAdd(&g_ssq[statL * 128 + tid], (double)red[128 + tid]);
    }
}

// ---------------- final: act7 -> logits -> softmax(K) -> gather+weighted sum ----------------
__global__ void k_final(const float* __restrict__ xfeat, const int* __restrict__ idx,
                        const float* __restrict__ fw, const float* __restrict__ fb,
                        float* __restrict__ out) {
    __shared__ float prod[20][128];
    __shared__ float wsm[20];
    __shared__ float logit[20];
    __shared__ int   idxs[20];

    const int m = blockIdx.x;
    const int tid = threadIdx.x;  // 128
    const float sc = g_scale[7 * 128 + tid];
    const float sh = g_shift[7 * 128 + tid];
    const float f  = fw[tid];
    const float* hrow = g_h + (long)m * 20 * 128;

    if (tid < 20) idxs[tid] = idx[m * 20 + tid];
#pragma unroll
    for (int k = 0; k < 20; k++) {
        float v = hrow[k * 128 + tid];
        prod[k][tid] = __sinf(fmaf(sc, v, sh)) * f;
    }
    __syncthreads();

    const int w = tid >> 5, lane = tid & 31;
    for (int k = w; k < 20; k += 4) {
        float sum = prod[k][lane] + prod[k][lane + 32] + prod[k][lane + 64] + prod[k][lane + 96];
        for (int off = 16; off; off >>= 1) sum += __shfl_down_sync(0xffffffffu, sum, off);
        if (lane == 0) logit[k] = sum + fb[0];
    }
    __syncthreads();

    if (tid < 32) {
        float l = (tid < 20) ? logit[tid] : -INFINITY;
        float mx = l;
        for (int off = 16; off; off >>= 1) mx = fmaxf(mx, __shfl_xor_sync(0xffffffffu, mx, off));
        float e = (tid < 20) ? expf(l - mx) : 0.f;
        float ss = e;
        for (int off = 16; off; off >>= 1) ss += __shfl_xor_sync(0xffffffffu, ss, off);
        if (tid < 20) wsm[tid] = e / ss;
    }
    __syncthreads();

    float acc = 0.f;
#pragma unroll
    for (int k = 0; k < 20; k++)
        acc += wsm[k] * xfeat[(long)idxs[k] * 128 + tid];
    out[(long)m * 128 + tid] = acc;
}

// ---------------- launch ----------------
extern "C" void kernel_launch(void* const* d_in, const int* in_sizes, int n_in,
                              void* d_out, int out_size) {
    const float* xfeat  = (const float*)d_in[0];  // (1, N, 128)
    const float* w_up   = (const float*)d_in[1];  // (1, 7, M, K)
    const int*   idx    = (const int*)d_in[2];    // (1, M, K)
    const float* conv0  = (const float*)d_in[3];  // (128, 7)
    const float* convs  = (const float*)d_in[4];  // (7, 128, 128)
    const float* gammas = (const float*)d_in[5];  // (8, 128)
    const float* betas  = (const float*)d_in[6];  // (8, 128)
    const float* fw     = (const float*)d_in[7];  // (1, 128)
    const float* fb     = (const float*)d_in[8];  // (1,)
    float* out = (float*)d_out;

    const int smem_bytes = SMEM_FLOATS * sizeof(float);
    cudaFuncSetAttribute(k_gemm, cudaFuncAttributeMaxDynamicSharedMemorySize, smem_bytes);

    k_zero<<<1, 256>>>();
    k_instats<<<256, 256>>>(w_up);
    k_fin0<<<1, 128>>>(conv0, gammas, betas);

    // Layer 1: act0 from raw input (conv0 via split-tf32 mma, BN0, sin), GEMM W1, stats
    k_gemm<<<NBLK, 256, smem_bytes>>>(w_up, convs, conv0, 0, 1, 0);
    k_fin<<<1, 128>>>(1, gammas, betas);

    // Layers 2..7
    for (int i = 2; i <= 7; i++) {
        k_gemm<<<NBLK, 256, smem_bytes>>>(nullptr, convs + (i - 1) * 16384, nullptr, i - 1, i, 1);
        k_fin<<<1, 128>>>(i, gammas, betas);
    }

    k_final<<<MM, 128>>>(xfeat, idx, fw, fb, out);
}

// round 10
// speedup vs baseline: 2.8929x; 2.2350x over previous
#include <cuda_runtime.h>
#include <math.h>
#include <stdint.h>

// Problem constants
#define MM    35637
#define KKN   20
#define MKP   712740          // MM*KKN points
#define EPSB  1e-5
#define NBLK  5569            // ceil(MKP/128)

#define APITCH 130            // A pair (8B) pitch per row
#define BPITCH 132            // B tf32 (4B) pitch per row

typedef unsigned int u32;
typedef unsigned long long ull;

// ---------------- device scratch (static: allocation-guard-safe) ----------------
__device__ float  g_h[91230720];        // 712740 x 128 pre-activations (in-place)
__device__ u32    g_Bt[7 * 128 * BPITCH];  // per-layer weights pre-rounded to tf32 (rna)
__device__ double g_sum[8 * 128];
__device__ double g_ssq[8 * 128];
__device__ float  g_scale[8 * 128];
__device__ float  g_shift[8 * 128];
__device__ double g_inS[7];
__device__ double g_inSS[28];

// ---------------- smem layout (bytes) ----------------
#define OFF_A2   0                                   // 128*130*8 = 133120
#define OFF_B    133120                              // 128*132*4 = 67584
#define OFF_RED  200704                              // 256 floats
#define OFF_SC   201728                              // 128 floats
#define OFF_SH   202240                              // 128 floats
#define OFF_X0   202752                              // 128*8 floats (mode0)
#define OFF_W0   206848                              // 128*8 floats (mode0)
#define SMEM_TOTAL 210944

// ---------------- helpers ----------------
static __device__ __forceinline__ u32 smem_u32(const void* p) {
    u32 a;
    asm("{ .reg .u64 t; cvta.to.shared.u64 t, %1; cvt.u32.u64 %0, t; }" : "=r"(a) : "l"(p));
    return a;
}
static __device__ __forceinline__ u32 tf32r(float x) {
    u32 r;
    asm("cvt.rna.tf32.f32 %0, %1;" : "=r"(r) : "f"(x));
    return r;
}
// FastF32 split: hi = masked (exact tf32), lo = residual
static __device__ __forceinline__ ull splitpack(float a) {
    u32 hb = __float_as_uint(a) & 0xFFFFE000u;
    float lo = a - __uint_as_float(hb);
    return (ull)hb | ((ull)__float_as_uint(lo) << 32);
}
static __device__ __forceinline__ void mma8(float* c, const u32* a, const u32* b) {
    asm volatile(
        "mma.sync.aligned.m16n8k8.row.col.f32.tf32.tf32.f32 "
        "{%0,%1,%2,%3}, {%4,%5,%6,%7}, {%8,%9}, {%0,%1,%2,%3};"
        : "+f"(c[0]), "+f"(c[1]), "+f"(c[2]), "+f"(c[3])
        : "r"(a[0]), "r"(a[1]), "r"(a[2]), "r"(a[3]), "r"(b[0]), "r"(b[1]));
}

// ---------------- zero accumulators (must rerun every graph replay) ----------------
__global__ void k_zero() {
    int t = threadIdx.x;
    for (int i = t; i < 1024; i += 256) { g_sum[i] = 0.0; g_ssq[i] = 0.0; }
    if (t < 7)  g_inS[t]  = 0.0;
    if (t < 28) g_inSS[t] = 0.0;
}

// ---------------- per-layer weight pre-round to tf32 (rna), padded pitch ----------------
__global__ void k_prep(const float* __restrict__ convs) {
    int i = blockIdx.x * blockDim.x + threadIdx.x;
    if (i >= 7 * 128 * BPITCH) return;
    int k = i % BPITCH;
    int rest = i / BPITCH;
    int o = rest & 127;
    int w = rest >> 7;
    g_Bt[i] = (k < 128) ? tf32r(convs[w * 16384 + o * 128 + k]) : 0u;
}

// ---------------- input stats: sum(x) [7] and sum(x x^T) [28 triangle] ----------------
__global__ void k_instats(const float* __restrict__ in7) {
    long stride = (long)gridDim.x * blockDim.x;
    float s[7], q[28];
#pragma unroll
    for (int j = 0; j < 7; j++) s[j] = 0.f;
#pragma unroll
    for (int t = 0; t < 28; t++) q[t] = 0.f;

    for (long p = (long)blockIdx.x * blockDim.x + threadIdx.x; p < MKP; p += stride) {
        float x[7];
#pragma unroll
        for (int j = 0; j < 7; j++) x[j] = in7[(long)j * MKP + p];
        int t = 0;
#pragma unroll
        for (int j = 0; j < 7; j++) {
            s[j] += x[j];
#pragma unroll
            for (int jj = j; jj < 7; jj++) { q[t] += x[j] * x[jj]; t++; }
        }
    }
#pragma unroll
    for (int j = 0; j < 7; j++)
        for (int off = 16; off; off >>= 1) s[j] += __shfl_down_sync(0xffffffffu, s[j], off);
#pragma unroll
    for (int t = 0; t < 28; t++)
        for (int off = 16; off; off >>= 1) q[t] += __shfl_down_sync(0xffffffffu, q[t], off);

    if ((threadIdx.x & 31) == 0) {
#pragma unroll
        for (int j = 0; j < 7; j++) atomicAdd(&g_inS[j], (double)s[j]);
#pragma unroll
        for (int t = 0; t < 28; t++) atomicAdd(&g_inSS[t], (double)q[t]);
    }
}

// ---------------- BN0 params analytically from input moments ----------------
__global__ void k_fin0(const float* __restrict__ W0,
                       const float* __restrict__ gammas,
                       const float* __restrict__ betas) {
    int c = threadIdx.x;  // 128
    double S[7], SS[7][7];
#pragma unroll
    for (int j = 0; j < 7; j++) S[j] = g_inS[j];
    int t = 0;
    for (int j = 0; j < 7; j++)
        for (int jj = j; jj < 7; jj++) { SS[j][jj] = g_inSS[t]; SS[jj][j] = g_inSS[t]; t++; }
    double w[7];
#pragma unroll
    for (int j = 0; j < 7; j++) w[j] = (double)W0[c * 7 + j];
    double mu = 0.0;
#pragma unroll
    for (int j = 0; j < 7; j++) mu += w[j] * S[j];
    mu /= (double)MKP;
    double e2 = 0.0;
    for (int j = 0; j < 7; j++)
        for (int jj = 0; jj < 7; jj++) e2 += w[j] * w[jj] * SS[j][jj];
    e2 /= (double)MKP;
    double var = e2 - mu * mu;
    double scl = (double)gammas[c] / sqrt(var + EPSB);
    g_scale[c] = (float)scl;
    g_shift[c] = (float)((double)betas[c] - mu * scl);
}

// ---------------- BN params for layer L ----------------
__global__ void k_fin(int L, const float* __restrict__ gammas, const float* __restrict__ betas) {
    int c = threadIdx.x;  // 128
    double mu  = g_sum[L * 128 + c] / (double)MKP;
    double var = g_ssq[L * 128 + c] / (double)MKP - mu * mu;
    double scl = (double)gammas[L * 128 + c] / sqrt(var + EPSB);
    g_scale[L * 128 + c] = (float)scl;
    g_shift[L * 128 + c] = (float)((double)betas[L * 128 + c] - mu * scl);
}

// ---------------- fused pass: act=sin(BN(h)), h' = act @ W^T (split-A tf32 mma), stats ----------------
// 512 threads, 16 warps (4x4 warp grid, 32x32 per warp). A pre-split into (hi,lo)
// pairs in smem; B pre-rounded tf32 pulled via cp.async; 2 MMA passes per k-step.
__global__ void __launch_bounds__(512, 1)
k_gemm(const float* __restrict__ src, const float* __restrict__ W0c,
       int wIdx, int actL, int statL, int mode) {
    extern __shared__ char sm[];
    ull*   As2 = (ull*)(sm + OFF_A2);
    u32*   Bt  = (u32*)(sm + OFF_B);
    float* red = (float*)(sm + OFF_RED);
    float* scs = (float*)(sm + OFF_SC);
    float* shs = (float*)(sm + OFF_SH);
    float* xs0 = (float*)(sm + OFF_X0);
    float* w0s = (float*)(sm + OFF_W0);

    const u32 sb   = smem_u32(sm);
    const int tid  = threadIdx.x;
    const int wid  = tid >> 5;
    const int lane = tid & 31;
    const int lg   = lane >> 2;
    const int lq   = lane & 3;
    const int wm   = wid & 3;     // 32-row band
    const int wn   = wid >> 2;    // 32-col band
    const long p0  = (long)blockIdx.x * 128;

    // --- async B tile fetch (pre-rounded tf32, linear copy incl. pad) ---
    {
        const u32* gsrc = g_Bt + (long)wIdx * (128 * BPITCH);
        u32 db = sb + OFF_B;
#pragma unroll 1
        for (int i = tid; i < (128 * BPITCH) / 4; i += 512) {
            asm volatile("cp.async.cg.shared.global [%0], [%1], 16;"
                         :: "r"(db + i * 16), "l"(gsrc + i * 4) : "memory");
        }
        asm volatile("cp.async.commit_group;" ::: "memory");
    }

    if (tid < 128) {
        scs[tid] = g_scale[actL * 128 + tid];
        shs[tid] = g_shift[actL * 128 + tid];
    }
    if (tid < 256) red[tid] = 0.f;
    if (mode == 0) {
        for (int t = tid; t < 1024; t += 512) {
            int p = t >> 3, j = t & 7;
            xs0[t] = (j < 7 && p0 + p < MKP) ? src[(long)j * MKP + p0 + p] : 0.f;
        }
        for (int t = tid; t < 1024; t += 512) {
            int c = t >> 3, j = t & 7;
            w0s[t] = (j < 7) ? W0c[c * 7 + j] : 0.f;
        }
    }
    __syncthreads();

    // --- activation tile: As2[p][c] = splitpack(sin(scale*h + shift)) ---
    // 4096 items total (128 rows x 32 col-quads) -> 8 iterations of 512 threads.
    if (mode == 0) {
#pragma unroll 2
        for (int j = 0; j < 8; j++) {
            int it = j * 512 + tid;
            int p = it >> 5, c4 = (it & 31) << 2;
            bool inb = (p0 + p < MKP);
            float xp[7];
#pragma unroll
            for (int jj = 0; jj < 7; jj++) xp[jj] = xs0[p * 8 + jj];
            ull pr[4];
#pragma unroll
            for (int e = 0; e < 4; e++) {
                int c = c4 + e;
                float v = 0.f;
#pragma unroll
                for (int jj = 0; jj < 7; jj++) v = fmaf(w0s[c * 8 + jj], xp[jj], v);
                float a = inb ? __sinf(fmaf(scs[c], v, shs[c])) : 0.f;
                pr[e] = splitpack(a);
            }
            ulonglong2* dst = (ulonglong2*)&As2[p * APITCH + c4];
            dst[0] = make_ulonglong2(pr[0], pr[1]);
            dst[1] = make_ulonglong2(pr[2], pr[3]);
        }
    } else {
#pragma unroll 4
        for (int j = 0; j < 8; j++) {
            int it = j * 512 + tid;
            int p = it >> 5, c4 = (it & 31) << 2;
            long pg = p0 + p;
            bool inb = (pg < MKP);
            float4 hv = inb ? *(const float4*)&g_h[pg * 128 + c4]
                            : make_float4(0.f, 0.f, 0.f, 0.f);
            ull pr[4];
            pr[0] = splitpack(inb ? __sinf(fmaf(scs[c4],     hv.x, shs[c4]))     : 0.f);
            pr[1] = splitpack(inb ? __sinf(fmaf(scs[c4 + 1], hv.y, shs[c4 + 1])) : 0.f);
            pr[2] = splitpack(inb ? __sinf(fmaf(scs[c4 + 2], hv.z, shs[c4 + 2])) : 0.f);
            pr[3] = splitpack(inb ? __sinf(fmaf(scs[c4 + 3], hv.w, shs[c4 + 3])) : 0.f);
            ulonglong2* dst = (ulonglong2*)&As2[p * APITCH + c4];
            dst[0] = make_ulonglong2(pr[0], pr[1]);
            dst[1] = make_ulonglong2(pr[2], pr[3]);
        }
    }
    asm volatile("cp.async.wait_group 0;" ::: "memory");
    __syncthreads();

    // --- main GEMM: 128x128x128, 2-pass split-A tf32 mma ---
    float acc[2][4][4];
#pragma unroll
    for (int mt = 0; mt < 2; mt++)
#pragma unroll
        for (int nt = 0; nt < 4; nt++)
#pragma unroll
            for (int e = 0; e < 4; e++) acc[mt][nt][e] = 0.f;

    const int r0 = wm * 32 + lg;
    const int n0 = wn * 32 + lg;

#pragma unroll 2
    for (int ks = 0; ks < 16; ks++) {
        int k0 = ks * 8 + lq;
        u32 ah[2][4], al[2][4];
#pragma unroll
        for (int mt = 0; mt < 2; mt++) {
            int r = r0 + mt * 16;
            ull pa0 = As2[r * APITCH + k0];
            ull pa1 = As2[(r + 8) * APITCH + k0];
            ull pa2 = As2[r * APITCH + k0 + 4];
            ull pa3 = As2[(r + 8) * APITCH + k0 + 4];
            ah[mt][0] = (u32)pa0; al[mt][0] = (u32)(pa0 >> 32);
            ah[mt][1] = (u32)pa1; al[mt][1] = (u32)(pa1 >> 32);
            ah[mt][2] = (u32)pa2; al[mt][2] = (u32)(pa2 >> 32);
            ah[mt][3] = (u32)pa3; al[mt][3] = (u32)(pa3 >> 32);
        }
#pragma unroll
        for (int nt = 0; nt < 4; nt++) {
            u32 b[2];
            b[0] = Bt[(n0 + nt * 8) * BPITCH + k0];
            b[1] = Bt[(n0 + nt * 8) * BPITCH + k0 + 4];
#pragma unroll
            for (int mt = 0; mt < 2; mt++) {
                mma8(acc[mt][nt], ah[mt], b);
                mma8(acc[mt][nt], al[mt], b);
            }
        }
    }

    // --- epilogue: store h_l, per-channel stats (shfl-reduced over lg) ---
#pragma unroll
    for (int mt = 0; mt < 2; mt++) {
        long rA = p0 + wm * 32 + mt * 16 + lg;
        long rB = rA + 8;
        bool vA = (rA < MKP), vB = (rB < MKP);
#pragma unroll
        for (int nt = 0; nt < 4; nt++) {
            int c0 = wn * 32 + nt * 8 + lq * 2;
            if (vA) *(float2*)&g_h[rA * 128 + c0] = make_float2(acc[mt][nt][0], acc[mt][nt][1]);
            if (vB) *(float2*)&g_h[rB * 128 + c0] = make_float2(acc[mt][nt][2], acc[mt][nt][3]);
        }
    }
#pragma unroll
    for (int nt = 0; nt < 4; nt++) {
        int c0 = wn * 32 + nt * 8 + lq * 2;
#pragma unroll
        for (int par = 0; par < 2; par++) {
            float v0 = acc[0][nt][par],     v1 = acc[0][nt][2 + par];
            float v2 = acc[1][nt][par],     v3 = acc[1][nt][2 + par];
            float s = (v0 + v1) + (v2 + v3);
            float q = fmaf(v0, v0, fmaf(v1, v1, fmaf(v2, v2, v3 * v3)));
            s += __shfl_xor_sync(0xffffffffu, s, 4);
            q += __shfl_xor_sync(0xffffffffu, q, 4);
            s += __shfl_xor_sync(0xffffffffu, s, 8);
            q += __shfl_xor_sync(0xffffffffu, q, 8);
            s += __shfl_xor_sync(0xffffffffu, s, 16);
            q += __shfl_xor_sync(0xffffffffu, q, 16);
            if (lg == 0) {
                atomicAdd(&red[c0 + par], s);
                atomicAdd(&red[128 + c0 + par], q);
            }
        }
    }
    __syncthreads();
    if (tid < 128) {
        atomicAdd(&g_sum[statL * 128 + tid], (double)red[tid]);
        atomicAdd(&g_ssq[statL * 128 + tid], (double)red[128 + tid]);
    }
}

// ---------------- final: act7 -> logits -> softmax(K) -> gather+weighted sum ----------------
__global__ void k_final(const float* __restrict__ xfeat, const int* __restrict__ idx,
                        const float* __restrict__ fw, const float* __restrict__ fb,
                        float* __restrict__ out) {
    __shared__ float prod[20][128];
    __shared__ float wsm[20];
    __shared__ float logit[20];
    __shared__ int   idxs[20];

    const int m = blockIdx.x;
    const int tid = threadIdx.x;  // 128
    const float sc = g_scale[7 * 128 + tid];
    const float sh = g_shift[7 * 128 + tid];
    const float f  = fw[tid];
    const float* hrow = g_h + (long)m * 20 * 128;

    if (tid < 20) idxs[tid] = idx[m * 20 + tid];
#pragma unroll
    for (int k = 0; k < 20; k++) {
        float v = hrow[k * 128 + tid];
        prod[k][tid] = __sinf(fmaf(sc, v, sh)) * f;
    }
    __syncthreads();

    const int w = tid >> 5, lane = tid & 31;
    for (int k = w; k < 20; k += 4) {
        float sum = prod[k][lane] + prod[k][lane + 32] + prod[k][lane + 64] + prod[k][lane + 96];
        for (int off = 16; off; off >>= 1) sum += __shfl_down_sync(0xffffffffu, sum, off);
        if (lane == 0) logit[k] = sum + fb[0];
    }
    __syncthreads();

    if (tid < 32) {
        float l = (tid < 20) ? logit[tid] : -INFINITY;
        float mx = l;
        for (int off = 16; off; off >>= 1) mx = fmaxf(mx, __shfl_xor_sync(0xffffffffu, mx, off));
        float e = (tid < 20) ? expf(l - mx) : 0.f;
        float ss = e;
        for (int off = 16; off; off >>= 1) ss += __shfl_xor_sync(0xffffffffu, ss, off);
        if (tid < 20) wsm[tid] = e / ss;
    }
    __syncthreads();

    float acc = 0.f;
#pragma unroll
    for (int k = 0; k < 20; k++)
        acc += wsm[k] * xfeat[(long)idxs[k] * 128 + tid];
    out[(long)m * 128 + tid] = acc;
}

// ---------------- launch ----------------
extern "C" void kernel_launch(void* const* d_in, const int* in_sizes, int n_in,
                              void* d_out, int out_size) {
    const float* xfeat  = (const float*)d_in[0];  // (1, N, 128)
    const float* w_up   = (const float*)d_in[1];  // (1, 7, M, K)
    const int*   idx    = (const int*)d_in[2];    // (1, M, K)
    const float* conv0  = (const float*)d_in[3];  // (128, 7)
    const float* convs  = (const float*)d_in[4];  // (7, 128, 128)
    const float* gammas = (const float*)d_in[5];  // (8, 128)
    const float* betas  = (const float*)d_in[6];  // (8, 128)
    const float* fw     = (const float*)d_in[7];  // (1, 128)
    const float* fb     = (const float*)d_in[8];  // (1,)
    float* out = (float*)d_out;

    cudaFuncSetAttribute(k_gemm, cudaFuncAttributeMaxDynamicSharedMemorySize, SMEM_TOTAL);

    k_zero<<<1, 256>>>();
    k_prep<<<(7 * 128 * BPITCH + 255) / 256, 256>>>(convs);
    k_instats<<<256, 256>>>(w_up);
    k_fin0<<<1, 128>>>(conv0, gammas, betas);

    // Layer 1: act0 from raw input (conv0 scalar + BN0 + sin), GEMM W1, stats
    k_gemm<<<NBLK, 512, SMEM_TOTAL>>>(w_up, conv0, 0, 0, 1, 0);
    k_fin<<<1, 128>>>(1, gammas, betas);

    // Layers 2..7
    for (int i = 2; i <= 7; i++) {
        k_gemm<<<NBLK, 512, SMEM_TOTAL>>>(nullptr, nullptr, i - 1, i - 1, i, 1);
        k_fin<<<1, 128>>>(i, gammas, betas);
    }

    k_final<<<MM, 128>>>(xfeat, idx, fw, fb, out);
}

// round 11
// speedup vs baseline: 3.4830x; 1.2040x over previous
#include <cuda_runtime.h>
#include <math.h>
#include <stdint.h>

// Problem constants
#define MM    35637
#define KKN   20
#define MKP   712740          // MM*KKN points
#define EPSB  1e-5
#define NBLK  5569            // ceil(MKP/128)

#define PKF   132             // pitch (floats) for A planes and B: 132 % 32 == 4 -> LDSM conflict-free
#define BPITCH 132

typedef unsigned int u32;
typedef unsigned long long ull;

// ---------------- device scratch (static: allocation-guard-safe) ----------------
__device__ float  g_h[91230720];        // 712740 x 128 pre-activations (in-place)
__device__ u32    g_Bt[7 * 128 * BPITCH];  // per-layer weights pre-rounded to tf32 (rna)
__device__ double g_sum[8 * 128];
__device__ double g_ssq[8 * 128];
__device__ float  g_scale[8 * 128];
__device__ float  g_shift[8 * 128];
__device__ double g_inS[7];
__device__ double g_inSS[28];

// ---------------- smem layout (bytes) ----------------
#define OFF_AH   0                       // A hi plane: 128*132*4 = 67584
#define OFF_AL   67584                   // A lo plane: 67584
#define OFF_B    135168                  // B tf32:     67584
#define OFF_RED  202752                  // 256 floats
#define OFF_SC   203776                  // 128 floats
#define OFF_SH   204288                  // 128 floats
#define OFF_X0   204800                  // 128*8 floats (mode0)
#define OFF_W0   208896                  // 128*8 floats (mode0)
#define SMEM_TOTAL 212992

#define ROWB (PKF * 4)                   // 528 bytes per row
#define MTOFF (16 * ROWB)                // 8448: 16-row block stride

// ---------------- helpers ----------------
static __device__ __forceinline__ u32 smem_u32(const void* p) {
    u32 a;
    asm("{ .reg .u64 t; cvta.to.shared.u64 t, %1; cvt.u32.u64 %0, t; }" : "=r"(a) : "l"(p));
    return a;
}
static __device__ __forceinline__ u32 tf32r(float x) {
    u32 r;
    asm("cvt.rna.tf32.f32 %0, %1;" : "=r"(r) : "f"(x));
    return r;
}
static __device__ __forceinline__ void ldsm4(u32* r, u32 addr) {
    asm volatile("ldmatrix.sync.aligned.m8n8.x4.shared.b16 {%0,%1,%2,%3}, [%4];"
                 : "=r"(r[0]), "=r"(r[1]), "=r"(r[2]), "=r"(r[3]) : "r"(addr));
}
static __device__ __forceinline__ void mma8(float* c, const u32* a, const u32* b) {
    asm volatile(
        "mma.sync.aligned.m16n8k8.row.col.f32.tf32.tf32.f32 "
        "{%0,%1,%2,%3}, {%4,%5,%6,%7}, {%8,%9}, {%0,%1,%2,%3};"
        : "+f"(c[0]), "+f"(c[1]), "+f"(c[2]), "+f"(c[3])
        : "r"(a[0]), "r"(a[1]), "r"(a[2]), "r"(a[3]), "r"(b[0]), "r"(b[1]));
}

// ---------------- zero accumulators (must rerun every graph replay) ----------------
__global__ void k_zero() {
    int t = threadIdx.x;
    for (int i = t; i < 1024; i += 256) { g_sum[i] = 0.0; g_ssq[i] = 0.0; }
    if (t < 7)  g_inS[t]  = 0.0;
    if (t < 28) g_inSS[t] = 0.0;
}

// ---------------- per-layer weight pre-round to tf32 (rna), padded pitch ----------------
__global__ void k_prep(const float* __restrict__ convs) {
    int i = blockIdx.x * blockDim.x + threadIdx.x;
    if (i >= 7 * 128 * BPITCH) return;
    int k = i % BPITCH;
    int rest = i / BPITCH;
    int o = rest & 127;
    int w = rest >> 7;
    g_Bt[i] = (k < 128) ? tf32r(convs[w * 16384 + o * 128 + k]) : 0u;
}

// ---------------- input stats: sum(x) [7] and sum(x x^T) [28 triangle] ----------------
__global__ void k_instats(const float* __restrict__ in7) {
    long stride = (long)gridDim.x * blockDim.x;
    float s[7], q[28];
#pragma unroll
    for (int j = 0; j < 7; j++) s[j] = 0.f;
#pragma unroll
    for (int t = 0; t < 28; t++) q[t] = 0.f;

    for (long p = (long)blockIdx.x * blockDim.x + threadIdx.x; p < MKP; p += stride) {
        float x[7];
#pragma unroll
        for (int j = 0; j < 7; j++) x[j] = in7[(long)j * MKP + p];
        int t = 0;
#pragma unroll
        for (int j = 0; j < 7; j++) {
            s[j] += x[j];
#pragma unroll
            for (int jj = j; jj < 7; jj++) { q[t] += x[j] * x[jj]; t++; }
        }
    }
#pragma unroll
    for (int j = 0; j < 7; j++)
        for (int off = 16; off; off >>= 1) s[j] += __shfl_down_sync(0xffffffffu, s[j], off);
#pragma unroll
    for (int t = 0; t < 28; t++)
        for (int off = 16; off; off >>= 1) q[t] += __shfl_down_sync(0xffffffffu, q[t], off);

    if ((threadIdx.x & 31) == 0) {
#pragma unroll
        for (int j = 0; j < 7; j++) atomicAdd(&g_inS[j], (double)s[j]);
#pragma unroll
        for (int t = 0; t < 28; t++) atomicAdd(&g_inSS[t], (double)q[t]);
    }
}

// ---------------- BN0 params analytically from input moments ----------------
__global__ void k_fin0(const float* __restrict__ W0,
                       const float* __restrict__ gammas,
                       const float* __restrict__ betas) {
    int c = threadIdx.x;  // 128
    double S[7], SS[7][7];
#pragma unroll
    for (int j = 0; j < 7; j++) S[j] = g_inS[j];
    int t = 0;
    for (int j = 0; j < 7; j++)
        for (int jj = j; jj < 7; jj++) { SS[j][jj] = g_inSS[t]; SS[jj][j] = g_inSS[t]; t++; }
    double w[7];
#pragma unroll
    for (int j = 0; j < 7; j++) w[j] = (double)W0[c * 7 + j];
    double mu = 0.0;
#pragma unroll
    for (int j = 0; j < 7; j++) mu += w[j] * S[j];
    mu /= (double)MKP;
    double e2 = 0.0;
    for (int j = 0; j < 7; j++)
        for (int jj = 0; jj < 7; jj++) e2 += w[j] * w[jj] * SS[j][jj];
    e2 /= (double)MKP;
    double var = e2 - mu * mu;
    double scl = (double)gammas[c] / sqrt(var + EPSB);
    g_scale[c] = (float)scl;
    g_shift[c] = (float)((double)betas[c] - mu * scl);
}

// ---------------- BN params for layer L ----------------
__global__ void k_fin(int L, const float* __restrict__ gammas, const float* __restrict__ betas) {
    int c = threadIdx.x;  // 128
    double mu  = g_sum[L * 128 + c] / (double)MKP;
    double var = g_ssq[L * 128 + c] / (double)MKP - mu * mu;
    double scl = (double)gammas[L * 128 + c] / sqrt(var + EPSB);
    g_scale[L * 128 + c] = (float)scl;
    g_shift[L * 128 + c] = (float)((double)betas[L * 128 + c] - mu * scl);
}

// ---------------- fused pass: act=sin(BN(h)), h' = act @ W^T (split-A tf32 mma), stats ----------------
// 512 threads, 16 warps (4x4 warp grid, 32x32 per warp). A split into hi/lo fp32
// planes; fragments loaded via ldmatrix.x4 (b16 aliasing, CUTLASS tf32 trick);
// B pre-rounded tf32 via cp.async; 2 MMA passes per k-step.
__global__ void __launch_bounds__(512, 1)
k_gemm(const float* __restrict__ src, const float* __restrict__ W0c,
       int wIdx, int actL, int statL, int mode) {
    extern __shared__ char sm[];
    float* AsH = (float*)(sm + OFF_AH);
    float* AsL = (float*)(sm + OFF_AL);
    float* red = (float*)(sm + OFF_RED);
    float* scs = (float*)(sm + OFF_SC);
    float* shs = (float*)(sm + OFF_SH);
    float* xs0 = (float*)(sm + OFF_X0);
    float* w0s = (float*)(sm + OFF_W0);

    const u32 sb   = smem_u32(sm);
    const int tid  = threadIdx.x;
    const int wid  = tid >> 5;
    const int lane = tid & 31;
    const int lg   = lane >> 2;
    const int lq   = lane & 3;
    const int wm   = wid & 3;     // 32-row band
    const int wn   = wid >> 2;    // 32-col band
    const long p0  = (long)blockIdx.x * 128;

    // --- async B tile fetch (pre-rounded tf32, linear copy incl. pad) ---
    {
        const u32* gsrc = g_Bt + (long)wIdx * (128 * BPITCH);
        u32 db = sb + OFF_B;
#pragma unroll 1
        for (int i = tid; i < (128 * BPITCH) / 4; i += 512) {
            asm volatile("cp.async.cg.shared.global [%0], [%1], 16;"
                         :: "r"(db + i * 16), "l"(gsrc + i * 4) : "memory");
        }
        asm volatile("cp.async.commit_group;" ::: "memory");
    }

    if (tid < 128) {
        scs[tid] = g_scale[actL * 128 + tid];
        shs[tid] = g_shift[actL * 128 + tid];
    }
    if (tid < 256) red[tid] = 0.f;
    if (mode == 0) {
        for (int t = tid; t < 1024; t += 512) {
            int p = t >> 3, j = t & 7;
            xs0[t] = (j < 7 && p0 + p < MKP) ? src[(long)j * MKP + p0 + p] : 0.f;
        }
        for (int t = tid; t < 1024; t += 512) {
            int c = t >> 3, j = t & 7;
            w0s[t] = (j < 7) ? W0c[c * 7 + j] : 0.f;
        }
    }
    __syncthreads();

    // --- activation tile: hi/lo planes of sin(scale*h + shift) ---
    // 4096 quad-items (128 rows x 32 col-quads), 8 iterations of 512 threads.
    if (mode == 0) {
#pragma unroll 2
        for (int j = 0; j < 8; j++) {
            int it = j * 512 + tid;
            int p = it >> 5, c4 = (it & 31) << 2;
            bool inb = (p0 + p < MKP);
            float xp[7];
#pragma unroll
            for (int jj = 0; jj < 7; jj++) xp[jj] = xs0[p * 8 + jj];
            float hi[4], lo[4];
#pragma unroll
            for (int e = 0; e < 4; e++) {
                int c = c4 + e;
                float v = 0.f;
#pragma unroll
                for (int jj = 0; jj < 7; jj++) v = fmaf(w0s[c * 8 + jj], xp[jj], v);
                float a = inb ? __sinf(fmaf(scs[c], v, shs[c])) : 0.f;
                u32 hb = __float_as_uint(a) & 0xFFFFE000u;
                hi[e] = __uint_as_float(hb);
                lo[e] = a - hi[e];
            }
            *(float4*)&AsH[p * PKF + c4] = make_float4(hi[0], hi[1], hi[2], hi[3]);
            *(float4*)&AsL[p * PKF + c4] = make_float4(lo[0], lo[1], lo[2], lo[3]);
        }
    } else {
        // prefetch all 8 rows first (MLP=8), then compute
        float4 hv[8];
#pragma unroll
        for (int j = 0; j < 8; j++) {
            int it = j * 512 + tid;
            int p = it >> 5, c4 = (it & 31) << 2;
            long pg = p0 + p;
            hv[j] = (pg < MKP) ? *(const float4*)&g_h[pg * 128 + c4]
                               : make_float4(0.f, 0.f, 0.f, 0.f);
        }
#pragma unroll
        for (int j = 0; j < 8; j++) {
            int it = j * 512 + tid;
            int p = it >> 5, c4 = (it & 31) << 2;
            bool inb = (p0 + p < MKP);
            float vv[4] = {hv[j].x, hv[j].y, hv[j].z, hv[j].w};
            float hi[4], lo[4];
#pragma unroll
            for (int e = 0; e < 4; e++) {
                float a = inb ? __sinf(fmaf(scs[c4 + e], vv[e], shs[c4 + e])) : 0.f;
                u32 hb = __float_as_uint(a) & 0xFFFFE000u;
                hi[e] = __uint_as_float(hb);
                lo[e] = a - hi[e];
            }
            *(float4*)&AsH[p * PKF + c4] = make_float4(hi[0], hi[1], hi[2], hi[3]);
            *(float4*)&AsL[p * PKF + c4] = make_float4(lo[0], lo[1], lo[2], lo[3]);
        }
    }
    asm volatile("cp.async.wait_group 0;" ::: "memory");
    __syncthreads();

    // --- main GEMM: 128x128x128, 2-pass split-A tf32 mma, ldmatrix fragments ---
    float acc[2][4][4];
#pragma unroll
    for (int mt = 0; mt < 2; mt++)
#pragma unroll
        for (int nt = 0; nt < 4; nt++)
#pragma unroll
            for (int e = 0; e < 4; e++) acc[mt][nt][e] = 0.f;

    // LDSM lane addresses:
    // A x4 tiles: (rows 0-7,k0-3),(rows 8-15,k0-3),(rows 0-7,k4-7),(rows 8-15,k4-7)
    //   -> regs a0,a1,a2,a3 of the m16n8k8 tf32 A fragment.
    const u32 aHiB = sb + OFF_AH + (u32)((wm * 32 + (lane & 15)) * ROWB) + ((lane >> 4) & 1) * 16;
    const u32 aLoB = aHiB + (OFF_AL - OFF_AH);
    // B x4 tiles: (nt0,k0-3),(nt0,k4-7),(nt1,k0-3),(nt1,k4-7) -> {b0,b1} x 2 nt.
    const u32 bB = sb + OFF_B
                 + (u32)((wn * 32 + (lane & 7) + ((lane >> 4) & 1) * 8) * ROWB)
                 + ((lane >> 3) & 1) * 16;

#pragma unroll 4
    for (int ks = 0; ks < 16; ks++) {
        const u32 kb = ks * 32;
        u32 ah0[4], ah1[4], al0[4], al1[4], bA[4], bC[4];
        ldsm4(ah0, aHiB + kb);
        ldsm4(ah1, aHiB + MTOFF + kb);
        ldsm4(al0, aLoB + kb);
        ldsm4(al1, aLoB + MTOFF + kb);
        ldsm4(bA, bB + kb);
        ldsm4(bC, bB + MTOFF + kb);

        mma8(acc[0][0], ah0, bA);     mma8(acc[0][0], al0, bA);
        mma8(acc[0][1], ah0, bA + 2); mma8(acc[0][1], al0, bA + 2);
        mma8(acc[0][2], ah0, bC);     mma8(acc[0][2], al0, bC);
        mma8(acc[0][3], ah0, bC + 2); mma8(acc[0][3], al0, bC + 2);
        mma8(acc[1][0], ah1, bA);     mma8(acc[1][0], al1, bA);
        mma8(acc[1][1], ah1, bA + 2); mma8(acc[1][1], al1, bA + 2);
        mma8(acc[1][2], ah1, bC);     mma8(acc[1][2], al1, bC);
        mma8(acc[1][3], ah1, bC + 2); mma8(acc[1][3], al1, bC + 2);
    }

    // --- epilogue: store h_l, per-channel stats (shfl-reduced over lg) ---
#pragma unroll
    for (int mt = 0; mt < 2; mt++) {
        long rA = p0 + wm * 32 + mt * 16 + lg;
        long rB = rA + 8;
        bool vA = (rA < MKP), vB = (rB < MKP);
#pragma unroll
        for (int nt = 0; nt < 4; nt++) {
            int c0 = wn * 32 + nt * 8 + lq * 2;
            if (vA) *(float2*)&g_h[rA * 128 + c0] = make_float2(acc[mt][nt][0], acc[mt][nt][1]);
            if (vB) *(float2*)&g_h[rB * 128 + c0] = make_float2(acc[mt][nt][2], acc[mt][nt][3]);
        }
    }
#pragma unroll
    for (int nt = 0; nt < 4; nt++) {
        int c0 = wn * 32 + nt * 8 + lq * 2;
#pragma unroll
        for (int par = 0; par < 2; par++) {
            float v0 = acc[0][nt][par],     v1 = acc[0][nt][2 + par];
            float v2 = acc[1][nt][par],     v3 = acc[1][nt][2 + par];
            float s = (v0 + v1) + (v2 + v3);
            float q = fmaf(v0, v0, fmaf(v1, v1, fmaf(v2, v2, v3 * v3)));
            s += __shfl_xor_sync(0xffffffffu, s, 4);
            q += __shfl_xor_sync(0xffffffffu, q, 4);
            s += __shfl_xor_sync(0xffffffffu, s, 8);
            q += __shfl_xor_sync(0xffffffffu, q, 8);
            s += __shfl_xor_sync(0xffffffffu, s, 16);
            q += __shfl_xor_sync(0xffffffffu, q, 16);
            if (lg == 0) {
                atomicAdd(&red[c0 + par], s);
                atomicAdd(&red[128 + c0 + par], q);
            }
        }
    }
    __syncthreads();
    if (tid < 128) {
        atomicAdd(&g_sum[statL * 128 + tid], (double)red[tid]);
        atomicAdd(&g_ssq[statL * 128 + tid], (double)red[128 + tid]);
    }
}

// ---------------- final: act7 -> logits -> softmax(K) -> gather+weighted sum ----------------
__global__ void k_final(const float* __restrict__ xfeat, const int* __restrict__ idx,
                        const float* __restrict__ fw, const float* __restrict__ fb,
                        float* __restrict__ out) {
    __shared__ float prod[20][128];
    __shared__ float wsm[20];
    __shared__ float logit[20];
    __shared__ int   idxs[20];

    const int m = blockIdx.x;
    const int tid = threadIdx.x;  // 128
    const float sc = g_scale[7 * 128 + tid];
    const float sh = g_shift[7 * 128 + tid];
    const float f  = fw[tid];
    const float* hrow = g_h + (long)m * 20 * 128;

    if (tid < 20) idxs[tid] = idx[m * 20 + tid];
#pragma unroll
    for (int k = 0; k < 20; k++) {
        float v = hrow[k * 128 + tid];
        prod[k][tid] = __sinf(fmaf(sc, v, sh)) * f;
    }
    __syncthreads();

    const int w = tid >> 5, lane = tid & 31;
    for (int k = w; k < 20; k += 4) {
        float sum = prod[k][lane] + prod[k][lane + 32] + prod[k][lane + 64] + prod[k][lane + 96];
        for (int off = 16; off; off >>= 1) sum += __shfl_down_sync(0xffffffffu, sum, off);
        if (lane == 0) logit[k] = sum + fb[0];
    }
    __syncthreads();

    if (tid < 32) {
        float l = (tid < 20) ? logit[tid] : -INFINITY;
        float mx = l;
        for (int off = 16; off; off >>= 1) mx = fmaxf(mx, __shfl_xor_sync(0xffffffffu, mx, off));
        float e = (tid < 20) ? expf(l - mx) : 0.f;
        float ss = e;
        for (int off = 16; off; off >>= 1) ss += __shfl_xor_sync(0xffffffffu, ss, off);
        if (tid < 20) wsm[tid] = e / ss;
    }
    __syncthreads();

    float acc = 0.f;
#pragma unroll
    for (int k = 0; k < 20; k++)
        acc += wsm[k] * xfeat[(long)idxs[k] * 128 + tid];
    out[(long)m * 128 + tid] = acc;
}

// ---------------- launch ----------------
extern "C" void kernel_launch(void* const* d_in, const int* in_sizes, int n_in,
                              void* d_out, int out_size) {
    const float* xfeat  = (const float*)d_in[0];  // (1, N, 128)
    const float* w_up   = (const float*)d_in[1];  // (1, 7, M, K)
    const int*   idx    = (const int*)d_in[2];    // (1, M, K)
    const float* conv0  = (const float*)d_in[3];  // (128, 7)
    const float* convs  = (const float*)d_in[4];  // (7, 128, 128)
    const float* gammas = (const float*)d_in[5];  // (8, 128)
    const float* betas  = (const float*)d_in[6];  // (8, 128)
    const float* fw     = (const float*)d_in[7];  // (1, 128)
    const float* fb     = (const float*)d_in[8];  // (1,)
    float* out = (float*)d_out;

    cudaFuncSetAttribute(k_gemm, cudaFuncAttributeMaxDynamicSharedMemorySize, SMEM_TOTAL);

    k_zero<<<1, 256>>>();
    k_prep<<<(7 * 128 * BPITCH + 255) / 256, 256>>>(convs);
    k_instats<<<256, 256>>>(w_up);
    k_fin0<<<1, 128>>>(conv0, gammas, betas);

    // Layer 1: act0 from raw input (conv0 scalar + BN0 + sin), GEMM W1, stats
    k_gemm<<<NBLK, 512, SMEM_TOTAL>>>(w_up, conv0, 0, 0, 1, 0);
    k_fin<<<1, 128>>>(1, gammas, betas);

    // Layers 2..7
    for (int i = 2; i <= 7; i++) {
        k_gemm<<<NBLK, 512, SMEM_TOTAL>>>(nullptr, nullptr, i - 1, i - 1, i, 1);
        k_fin<<<1, 128>>>(i, gammas, betas);
    }

    k_final<<<MM, 128>>>(xfeat, idx, fw, fb, out);
}